// round 2
// baseline (speedup 1.0000x reference)
#include <cuda_runtime.h>
#include <math.h>

#define BB 64
#define SS 512
#define FF 128
#define UU 512
#define TT 511            // S-1
#define SIGD 16512        // F + F*F

// ---------------- scratch (static device memory; no allocations) ----------------
static __device__ float d_A  [BB*TT*FF];    // prev + 0.5*dx   (16.7 MB)
static __device__ float d_dx [BB*TT*FF];    // dx              (16.7 MB)
static __device__ float d_sig[BB*SIGD];     // [s1 | s2]       (4.2 MB)
static __device__ float d_c1 [BB*UU];       // sig @ g_w1
static __device__ float d_c2 [BB*UU];       // sig @ g_skip_w
static __device__ float d_h1 [BB*UU];
static __device__ float d_h2 [BB*UU];
static __device__ float d_t3 [BB*UU];
static __device__ float d_t4 [BB*UU];
static __device__ float d_y  [BB*UU];
static __device__ float d_attn[BB*UU];      // softmax / S  (already scaled)
static __device__ float d_aggs[BB*FF];      // sum_s w*silu(x)
static __device__ float d_aggb[BB*FF*8];    // sum_s w*bspline_k(x)
static __device__ float d_cur [BB*UU];
static __device__ float d_spT [FF*8*UU];    // spline_w transposed -> [f*8+k][u]
static __device__ float d_g4  [4*BB*UU];    // gates f,i,c,o pre-activation

// ---------------- helpers ----------------
__device__ __forceinline__ float sigm(float x) {
    return __fdividef(1.f, 1.f + __expf(-x));
}

// level-3 B-spline basis (GRID_SIZE=5, ORDER=3) on uniform grid matching the
// reference's fp32 grid construction. Denominator reciprocals constant-fold.
__device__ __forceinline__ void bspline8(float x, float bs[8]) {
    float g[12];
#pragma unroll
    for (int j = 0; j < 12; ++j) g[j] = -1.0f + 0.4f * (float)(j - 3);
    float b0[11];
#pragma unroll
    for (int j = 0; j < 11; ++j) b0[j] = (x >= g[j] && x < g[j + 1]) ? 1.f : 0.f;
#pragma unroll
    for (int p = 1; p <= 3; ++p) {
#pragma unroll
        for (int j = 0; j + p < 11; ++j) {
            float left  = (x - g[j])       * (1.0f / (g[j + p] - g[j]));
            float right = (g[j + p + 1]-x) * (1.0f / (g[j + p + 1] - g[j + 1]));
            b0[j] = left * b0[j] + right * b0[j + 1];
        }
    }
#pragma unroll
    for (int k = 0; k < 8; ++k) bs[k] = b0[k];
}

// ---------------- kernels ----------------

// zero all atomically-accumulated buffers (launch 65536 threads)
__global__ void zero_kernel() {
    int i = blockIdx.x * blockDim.x + threadIdx.x;
    if (i < BB * FF * 8) d_aggb[i] = 0.f;
    if (i < BB * UU) {
        d_c1[i] = 0.f; d_c2[i] = 0.f; d_h2[i] = 0.f; d_t3[i] = 0.f;
        d_t4[i] = 0.f; d_cur[i] = 0.f;
        d_g4[i] = 0.f; d_g4[BB*UU + i] = 0.f;
        d_g4[2*BB*UU + i] = 0.f; d_g4[3*BB*UU + i] = 0.f;
    }
    if (i < BB * FF) d_aggs[i] = 0.f;
}

// per-(b,f) scan over t: dx, A = prefix + 0.5*dx, and s1 into sig
__global__ void scan_kernel(const float* __restrict__ in,
                            const float* __restrict__ tk) {
    __shared__ float tks[SS];
    int b = blockIdx.x, f = threadIdx.x;
    for (int i = f; i < SS; i += 128) tks[i] = tk[i];
    __syncthreads();
    const float* ip = in + (size_t)b * SS * FF + f;
    float cs = 0.f;
    float xp = tks[0] * ip[0];
#pragma unroll 4
    for (int t = 0; t < TT; ++t) {
        float x = tks[t + 1] * ip[(t + 1) * FF];
        float d = x - xp;
        int off = (b * TT + t) * FF + f;
        d_dx[off] = d;
        d_A [off] = cs + 0.5f * d;
        cs += d;
        xp = x;
    }
    d_sig[(size_t)b * SIGD + f] = cs;
}

// s2[b,i,j] = sum_t A[b,t,i]*dx[b,t,j]; grid (64 b, 8 jtiles), block 256
#define KC2 16
__global__ void s2_kernel() {
    __shared__ float Ak[KC2][FF];
    __shared__ float Dk[KC2][64];
    int b = blockIdx.x;
    int j0 = blockIdx.y * 64;
    int tid = threadIdx.x;
    int tx = tid & 15, ty = tid >> 4;
    float acc[8][4] = {};
    const float* Ab = d_A  + (size_t)b * TT * FF;
    const float* Db = d_dx + (size_t)b * TT * FF;
    for (int k0 = 0; k0 < TT; k0 += KC2) {
        for (int idx = tid; idx < KC2 * FF; idx += 256) {
            int kk = idx >> 7, i = idx & 127;
            int k = k0 + kk;
            Ak[kk][i] = (k < TT) ? Ab[k * FF + i] : 0.f;
        }
        for (int idx = tid; idx < KC2 * 64; idx += 256) {
            int kk = idx >> 6, j = idx & 63;
            int k = k0 + kk;
            Dk[kk][j] = (k < TT) ? Db[k * FF + j0 + j] : 0.f;
        }
        __syncthreads();
#pragma unroll
        for (int kk = 0; kk < KC2; ++kk) {
            float a[8], dv[4];
#pragma unroll
            for (int r = 0; r < 8; ++r) a[r] = Ak[kk][ty * 8 + r];
#pragma unroll
            for (int c = 0; c < 4; ++c) dv[c] = Dk[kk][tx * 4 + c];
#pragma unroll
            for (int r = 0; r < 8; ++r)
#pragma unroll
                for (int c = 0; c < 4; ++c)
                    acc[r][c] += a[r] * dv[c];
        }
        __syncthreads();
    }
    float* out = d_sig + (size_t)b * SIGD + FF;
#pragma unroll
    for (int r = 0; r < 8; ++r)
#pragma unroll
        for (int c = 0; c < 4; ++c)
            out[(ty * 8 + r) * FF + j0 + tx * 4 + c] = acc[r][c];
}

// generic C[64xN] += A[64xK] @ W[KxN] (row-major), N tiled by 64 (grid.x),
// K split across grid.y with fp32 atomics. block 256, 4x4 register tiles.
#define KCG 16
__global__ void gemm64_kernel(const float* __restrict__ A, int lda,
                              const float* __restrict__ W, int ldw,
                              float* __restrict__ C, int K) {
    __shared__ float As[64][KCG + 1];
    __shared__ float Ws[KCG][64];
    int tid = threadIdx.x;
    int tx = tid & 15, ty = tid >> 4;
    int j0 = blockIdx.x * 64;
    int kchunk = (K + gridDim.y - 1) / gridDim.y;
    int kbeg = blockIdx.y * kchunk;
    int kend = min(K, kbeg + kchunk);
    float acc[4][4] = {};
    for (int k0 = kbeg; k0 < kend; k0 += KCG) {
        for (int idx = tid; idx < 64 * KCG; idx += 256) {
            int bi = idx >> 4, kk = idx & 15;
            int k = k0 + kk;
            As[bi][kk] = (k < kend) ? A[(size_t)bi * lda + k] : 0.f;
        }
        for (int idx = tid; idx < KCG * 64; idx += 256) {
            int kk = idx >> 6, j = idx & 63;
            int k = k0 + kk;
            Ws[kk][j] = (k < kend) ? W[(size_t)k * ldw + j0 + j] : 0.f;
        }
        __syncthreads();
#pragma unroll
        for (int kk = 0; kk < KCG; ++kk) {
            float a[4], w[4];
#pragma unroll
            for (int r = 0; r < 4; ++r) a[r] = As[ty * 4 + r][kk];
#pragma unroll
            for (int c = 0; c < 4; ++c) w[c] = Ws[kk][tx * 4 + c];
#pragma unroll
            for (int r = 0; r < 4; ++r)
#pragma unroll
                for (int c = 0; c < 4; ++c)
                    acc[r][c] += a[r] * w[c];
        }
        __syncthreads();
    }
#pragma unroll
    for (int r = 0; r < 4; ++r)
#pragma unroll
        for (int c = 0; c < 4; ++c)
            atomicAdd(&C[(ty * 4 + r) * UU + j0 + tx * 4 + c], acc[r][c]);
}

// elementwise stages
__global__ void elu_kernel(const float* __restrict__ b1) {
    int i = blockIdx.x * blockDim.x + threadIdx.x;
    float v = d_c1[i] + b1[i & 511];
    d_h1[i] = v > 0.f ? v : expm1f(v);
}
__global__ void addbias_kernel(const float* __restrict__ b2) {
    int i = blockIdx.x * blockDim.x + threadIdx.x;
    d_h2[i] += b2[i & 511];
}
__global__ void glu_kernel(const float* __restrict__ b3,
                           const float* __restrict__ b4,
                           const float* __restrict__ bskip) {
    int i = blockIdx.x * blockDim.x + threadIdx.x;
    float g = sigm(d_t3[i] + b3[i & 511]);
    d_y[i] = d_c2[i] + bskip[i & 511] + g * (d_t4[i] + b4[i & 511]);
}

// layernorm (eps=1e-3) + softmax, stores attn/S. grid 64, block 512
__global__ void lnsm_kernel(const float* __restrict__ gamma,
                            const float* __restrict__ beta) {
    __shared__ float red[512];
    int b = blockIdx.x, t = threadIdx.x;
    float v = d_y[b * UU + t];
    red[t] = v; __syncthreads();
    for (int s = 256; s > 0; s >>= 1) { if (t < s) red[t] += red[t + s]; __syncthreads(); }
    float mu = red[0] * (1.f / 512.f);
    __syncthreads();
    float dv = v - mu;
    red[t] = dv * dv; __syncthreads();
    for (int s = 256; s > 0; s >>= 1) { if (t < s) red[t] += red[t + s]; __syncthreads(); }
    float var = red[0] * (1.f / 512.f);
    __syncthreads();
    float yn = dv * rsqrtf(var + 1e-3f) * gamma[t] + beta[t];
    red[t] = yn; __syncthreads();
    for (int s = 256; s > 0; s >>= 1) { if (t < s) red[t] = fmaxf(red[t], red[t + s]); __syncthreads(); }
    float m = red[0];
    __syncthreads();
    float e = __expf(yn - m);
    red[t] = e; __syncthreads();
    for (int s = 256; s > 0; s >>= 1) { if (t < s) red[t] += red[t + s]; __syncthreads(); }
    float inv = __fdividef(1.f, red[0] * 512.f);
    d_attn[b * UU + t] = e * inv;
}

// attention-weighted KAN feature aggregation. grid (64 b, 8 s-chunks), block 128
__global__ void agg_kernel(const float* __restrict__ in,
                           const float* __restrict__ tk) {
    __shared__ float ws[64], tks[64];
    int b = blockIdx.x;
    int s0 = blockIdx.y * 64;
    int f = threadIdx.x;
    if (f < 64) {
        ws[f]  = d_attn[b * UU + s0 + f];
        tks[f] = tk[s0 + f];
    }
    __syncthreads();
    float sacc = 0.f;
    float bacc[8] = {};
    const float* ip = in + (size_t)b * SS * FF + (size_t)s0 * FF + f;
    for (int si = 0; si < 64; ++si) {
        float x = tks[si] * ip[si * FF];
        float w = ws[si];
        float sg = sigm(x);
        sacc += w * (x * sg);
        float bs[8];
        bspline8(x, bs);
#pragma unroll
        for (int k = 0; k < 8; ++k) bacc[k] += w * bs[k];
    }
    atomicAdd(&d_aggs[b * FF + f], sacc);
#pragma unroll
    for (int k = 0; k < 8; ++k)
        atomicAdd(&d_aggb[(b * FF + f) * 8 + k], bacc[k]);
}

// spline_w (U, F*8) -> spT (F*8, U), tiled transpose
__global__ void transpose_kernel(const float* __restrict__ sw) {
    __shared__ float tile[32][33];
    int fk0 = blockIdx.x * 32, u0 = blockIdx.y * 32;
    int tx = threadIdx.x, ty = threadIdx.y;
    for (int r = ty; r < 32; r += 8)
        tile[r][tx] = sw[(size_t)(u0 + r) * 1024 + fk0 + tx];
    __syncthreads();
    for (int r = ty; r < 32; r += 8)
        d_spT[(size_t)(fk0 + r) * 512 + u0 + tx] = tile[tx][r];
}

// final LSTM cell; writes [h_new | c_new] to out
__global__ void lstm_kernel(const float* __restrict__ c_prev,
                            const float* __restrict__ bf,
                            const float* __restrict__ bi_,
                            const float* __restrict__ bc,
                            const float* __restrict__ bo,
                            float* __restrict__ out) {
    int i = blockIdx.x * blockDim.x + threadIdx.x;
    int u = i & 511;
    float f  = sigm(d_g4[i]              + bf [u]);
    float ig = sigm(d_g4[BB*UU + i]      + bi_[u]);
    float cd = tanhf(d_g4[2*BB*UU + i]   + bc [u]);
    float o  = sigm(d_g4[3*BB*UU + i]    + bo [u]);
    float cn = f * c_prev[i] + ig * cd;
    out[i] = o * tanhf(cn);
    out[BB*UU + i] = cn;
}

// ---------------- host ----------------
extern "C" void kernel_launch(void* const* d_in, const int* in_sizes, int n_in,
                              void* d_out, int out_size) {
    const float* in       = (const float*)d_in[0];
    const float* h_prev   = (const float*)d_in[1];
    const float* c_prev   = (const float*)d_in[2];
    const float* tk       = (const float*)d_in[3];
    const float* base_w   = (const float*)d_in[4];
    const float* spline_w = (const float*)d_in[5];
    const float* g_w1     = (const float*)d_in[6];
    const float* g_b1     = (const float*)d_in[7];
    const float* g_w2     = (const float*)d_in[8];
    const float* g_b2     = (const float*)d_in[9];
    const float* g_w3     = (const float*)d_in[10];
    const float* g_b3     = (const float*)d_in[11];
    const float* g_w4     = (const float*)d_in[12];
    const float* g_b4     = (const float*)d_in[13];
    const float* g_skip_w = (const float*)d_in[14];
    const float* g_skip_b = (const float*)d_in[15];
    const float* ln_gamma = (const float*)d_in[16];
    const float* ln_beta  = (const float*)d_in[17];
    const float* wf       = (const float*)d_in[18];
    const float* bf       = (const float*)d_in[19];
    const float* wi       = (const float*)d_in[20];
    const float* bi       = (const float*)d_in[21];
    const float* wc       = (const float*)d_in[22];
    const float* bc       = (const float*)d_in[23];
    const float* wo       = (const float*)d_in[24];
    const float* bo       = (const float*)d_in[25];
    float* out = (float*)d_out;
    (void)in_sizes; (void)n_in; (void)out_size;

    float *p_sig, *p_c1, *p_c2, *p_h1, *p_h2, *p_t3, *p_t4;
    float *p_aggs, *p_aggb, *p_cur, *p_spT, *p_g4;
    cudaGetSymbolAddress((void**)&p_sig,  d_sig);
    cudaGetSymbolAddress((void**)&p_c1,   d_c1);
    cudaGetSymbolAddress((void**)&p_c2,   d_c2);
    cudaGetSymbolAddress((void**)&p_h1,   d_h1);
    cudaGetSymbolAddress((void**)&p_h2,   d_h2);
    cudaGetSymbolAddress((void**)&p_t3,   d_t3);
    cudaGetSymbolAddress((void**)&p_t4,   d_t4);
    cudaGetSymbolAddress((void**)&p_aggs, d_aggs);
    cudaGetSymbolAddress((void**)&p_aggb, d_aggb);
    cudaGetSymbolAddress((void**)&p_cur,  d_cur);
    cudaGetSymbolAddress((void**)&p_spT,  d_spT);
    cudaGetSymbolAddress((void**)&p_g4,   d_g4);

    zero_kernel<<<256, 256>>>();
    scan_kernel<<<64, 128>>>(in, tk);
    transpose_kernel<<<dim3(32, 16), dim3(32, 8)>>>(spline_w);   // independent
    s2_kernel<<<dim3(64, 8), 256>>>();

    // sig @ g_w1 and sig @ g_skip_w  (K = 16512, split 16)
    gemm64_kernel<<<dim3(8, 16), 256>>>(p_sig, SIGD, g_w1,     UU, p_c1, SIGD);
    gemm64_kernel<<<dim3(8, 16), 256>>>(p_sig, SIGD, g_skip_w, UU, p_c2, SIGD);

    elu_kernel<<<128, 256>>>(g_b1);
    gemm64_kernel<<<dim3(8, 4), 256>>>(p_h1, UU, g_w2, UU, p_h2, UU);
    addbias_kernel<<<128, 256>>>(g_b2);
    gemm64_kernel<<<dim3(8, 4), 256>>>(p_h2, UU, g_w3, UU, p_t3, UU);
    gemm64_kernel<<<dim3(8, 4), 256>>>(p_h2, UU, g_w4, UU, p_t4, UU);
    glu_kernel<<<128, 256>>>(g_b3, g_b4, g_skip_b);
    lnsm_kernel<<<64, 512>>>(ln_gamma, ln_beta);

    agg_kernel<<<dim3(64, 8), 128>>>(in, tk);

    // current = aggs @ base_w + aggb @ spline_wT
    gemm64_kernel<<<dim3(8, 2), 256>>>(p_aggs, FF,     base_w, UU, p_cur, FF);
    gemm64_kernel<<<dim3(8, 8), 256>>>(p_aggb, FF * 8, p_spT,  UU, p_cur, FF * 8);

    // gates: combined = [current | h_prev], split each weight matrix in two
    const float* Wg[4] = {wf, wi, wc, wo};
    for (int g = 0; g < 4; ++g) {
        gemm64_kernel<<<dim3(8, 4), 256>>>(p_cur,  UU, Wg[g],                    UU,
                                           p_g4 + (size_t)g * BB * UU, UU);
        gemm64_kernel<<<dim3(8, 4), 256>>>(h_prev, UU, Wg[g] + (size_t)512 * 512, UU,
                                           p_g4 + (size_t)g * BB * UU, UU);
    }

    lstm_kernel<<<128, 256>>>(c_prev, bf, bi, bc, bo, out);
}

// round 3
// speedup vs baseline: 3.4072x; 3.4072x over previous
#include <cuda_runtime.h>
#include <math.h>

#define BB 64
#define SS 512
#define FF 128
#define UU 512
#define TT 511            // S-1
#define SIGD 16512        // F + F*F

typedef unsigned long long ull;

// ---------------- scratch (static device memory; no allocations) ----------------
static __device__ float d_sig[BB*SIGD];     // [s1 | s2]       (4.2 MB)
static __device__ float d_c1 [BB*UU];       // sig @ g_w1
static __device__ float d_c2 [BB*UU];       // sig @ g_skip_w
static __device__ float d_h1 [BB*UU];
static __device__ float d_h2 [BB*UU];
static __device__ float d_t3 [BB*UU];
static __device__ float d_t4 [BB*UU];
static __device__ float d_attn[BB*UU];      // softmax / S  (already scaled)
static __device__ float d_aggs[BB*FF];      // sum_s w*silu(x)
static __device__ float d_aggb[BB*FF*8];    // sum_s w*bspline_k(x)
static __device__ float d_cur [BB*UU];
static __device__ float d_spT [FF*8*UU];    // spline_w transposed -> [f*8+k][u]
static __device__ float d_g4  [4*BB*UU];    // gates f,i,c,o pre-activation

// ---------------- helpers ----------------
__device__ __forceinline__ float sigm(float x) {
    return __fdividef(1.f, 1.f + __expf(-x));
}
__device__ __forceinline__ void fma2(ull &d, ull a, ull b) {
    asm("fma.rn.f32x2 %0, %1, %2, %0;" : "+l"(d) : "l"(a), "l"(b));
}
__device__ __forceinline__ ull splat2(float x) {
    ull r; asm("mov.b64 %0, {%1, %1};" : "=l"(r) : "f"(x)); return r;
}
__device__ __forceinline__ void unpack2(ull v, float &lo, float &hi) {
    asm("mov.b64 {%0, %1}, %2;" : "=f"(lo), "=f"(hi) : "l"(v));
}

// level-3 B-spline basis (GRID_SIZE=5, ORDER=3), denominators constant-fold
__device__ __forceinline__ void bspline8(float x, float bs[8]) {
    float g[12];
#pragma unroll
    for (int j = 0; j < 12; ++j) g[j] = -1.0f + 0.4f * (float)(j - 3);
    float b0[11];
#pragma unroll
    for (int j = 0; j < 11; ++j) b0[j] = (x >= g[j] && x < g[j + 1]) ? 1.f : 0.f;
#pragma unroll
    for (int p = 1; p <= 3; ++p) {
#pragma unroll
        for (int j = 0; j + p < 11; ++j) {
            float left  = (x - g[j])       * (1.0f / (g[j + p] - g[j]));
            float right = (g[j + p + 1]-x) * (1.0f / (g[j + p + 1] - g[j + 1]));
            b0[j] = left * b0[j] + right * b0[j + 1];
        }
    }
#pragma unroll
    for (int k = 0; k < 8; ++k) bs[k] = b0[k];
}

// ---------------- kernels ----------------

// zero all atomically-accumulated buffers (65536 threads)
__global__ void zero_kernel() {
    int i = blockIdx.x * blockDim.x + threadIdx.x;
    if (i < BB * FF * 8) d_aggb[i] = 0.f;
    if (i < BB * UU) {
        d_c1[i] = 0.f; d_c2[i] = 0.f; d_h2[i] = 0.f; d_t3[i] = 0.f;
        d_t4[i] = 0.f; d_cur[i] = 0.f;
        d_g4[i] = 0.f; d_g4[BB*UU + i] = 0.f;
        d_g4[2*BB*UU + i] = 0.f; d_g4[3*BB*UU + i] = 0.f;
    }
    if (i < BB * FF) d_aggs[i] = 0.f;
}

// ---------------- fused signature kernel ----------------
// Computes dx on the fly from input, carries the cumulative sum (prefix) in
// registers, emits s1 and s2 = sum_t (prev + 0.5 dx) (x) dx directly.
// grid (64 b, 2 jhalf), block 256. Tiles: rows 128 (all i), cols 64.
__global__ void s2f_kernel(const float* __restrict__ in,
                           const float* __restrict__ tk) {
    __shared__ __align__(16) float xc [16][FF];
    __shared__ __align__(16) float dxc[16][FF];
    __shared__ __align__(16) float Ak [16][FF];
    __shared__ float xprev[FF];
    __shared__ float tks[SS];
    int b  = blockIdx.x;
    int j0 = blockIdx.y * 64;
    int tid = threadIdx.x;
    int tx = tid & 15, ty = tid >> 4;     // cols: tx*4 (+0..3); row pairs: ty*8 + 2*r2
    const float* ib = in + (size_t)b * SS * FF;

    for (int i = tid; i < SS; i += 256) tks[i] = tk[i];
    __syncthreads();
    if (tid < FF) xprev[tid] = tks[0] * ib[tid];
    float run = 0.f;
    __syncthreads();

    ull acc[4][4];
#pragma unroll
    for (int r = 0; r < 4; ++r)
#pragma unroll
        for (int c = 0; c < 4; ++c) acc[r][c] = 0ULL;

    for (int k0 = 0; k0 < TT; k0 += 16) {
        // load 16 new x rows (t = k0+1 .. k0+16)
#pragma unroll
        for (int s = 0; s < 8; ++s) {
            int e = tid + s * 256;
            int kk = e >> 7, f = e & 127;
            int t1 = k0 + kk + 1;
            xc[kk][f] = (t1 < SS) ? tks[t1] * ib[(size_t)t1 * FF + f] : 0.f;
        }
        __syncthreads();
        // dx
#pragma unroll
        for (int s = 0; s < 8; ++s) {
            int e = tid + s * 256;
            int kk = e >> 7, f = e & 127;
            float prev = kk ? xc[kk - 1][f] : xprev[f];
            dxc[kk][f] = (k0 + kk < TT) ? xc[kk][f] - prev : 0.f;
        }
        __syncthreads();
        // sequential prefix within chunk (threads 0..127, one feature each)
        if (tid < FF) {
            int f = tid;
            float r = run;
#pragma unroll
            for (int kk = 0; kk < 16; ++kk) {
                float d = dxc[kk][f];
                Ak[kk][f] = r + 0.5f * d;
                r += d;
            }
            run = r;
            xprev[f] = xc[15][f];
        }
        __syncthreads();
        // MMA: acc[i pair][j] += Ak[kk][i] * dxc[kk][j]
#pragma unroll
        for (int kk = 0; kk < 16; ++kk) {
            const ull* ap = (const ull*)(&Ak[kk][ty * 8]);
            ull a2[4];
#pragma unroll
            for (int r = 0; r < 4; ++r) a2[r] = ap[r];
#pragma unroll
            for (int c = 0; c < 4; ++c) {
                ull dsp = splat2(dxc[kk][j0 + tx * 4 + c]);
#pragma unroll
                for (int r = 0; r < 4; ++r) fma2(acc[r][c], a2[r], dsp);
            }
        }
        __syncthreads();
    }

    float* out = d_sig + (size_t)b * SIGD + FF;
#pragma unroll
    for (int r = 0; r < 4; ++r)
#pragma unroll
        for (int c = 0; c < 4; ++c) {
            float lo, hi; unpack2(acc[r][c], lo, hi);
            int i = ty * 8 + 2 * r;
            int j = j0 + tx * 4 + c;
            out[(size_t)i * FF + j] = lo;
            out[(size_t)(i + 1) * FF + j] = hi;
        }
    if (j0 == 0 && tid < FF) d_sig[(size_t)b * SIGD + tid] = run;
}

// ---------------- generic 64xN GEMM core (N tile 128, f32x2 inner) ----------------
#define KC 16
__device__ __forceinline__ void gemm_core(const float* __restrict__ A, int lda,
                                          const float* __restrict__ W,
                                          float* __restrict__ C,
                                          int kbeg, int kend) {
    __shared__ __align__(16) float As[64][20];
    __shared__ __align__(16) float Ws[KC][128];
    int tid = threadIdx.x;
    int tx = tid & 15, ty = tid >> 4;          // cols: tx*8 (8 each), rows: ty*4 (4 each)
    int j0 = blockIdx.x * 128;
    ull acc[4][4];
#pragma unroll
    for (int r = 0; r < 4; ++r)
#pragma unroll
        for (int c = 0; c < 4; ++c) acc[r][c] = 0ULL;

    for (int k0 = kbeg; k0 < kend; k0 += KC) {
        // A tile: 64 rows x 16 k as float4 (all K boundaries are multiples of 4)
        {
            int row = tid >> 2, kq = (tid & 3) * 4;
            int k = k0 + kq;
            float4 v = make_float4(0.f, 0.f, 0.f, 0.f);
            if (k < kend) v = *(const float4*)(A + (size_t)row * lda + k);
            *(float4*)(&As[row][kq]) = v;
        }
        // W tile: 16 k x 128 j as float4, coalesced
#pragma unroll
        for (int s = 0; s < 2; ++s) {
            int e = tid + s * 256;
            int kk = e >> 5, jq = (e & 31) * 4;
            int k = k0 + kk;
            float4 v = make_float4(0.f, 0.f, 0.f, 0.f);
            if (k < kend) v = *(const float4*)(W + (size_t)k * UU + j0 + jq);
            *(float4*)(&Ws[kk][jq]) = v;
        }
        __syncthreads();
#pragma unroll
        for (int kk = 0; kk < KC; ++kk) {
            const ull* wp = (const ull*)(&Ws[kk][tx * 8]);
            ull w2[4];
#pragma unroll
            for (int c = 0; c < 4; ++c) w2[c] = wp[c];
#pragma unroll
            for (int r = 0; r < 4; ++r) {
                ull asp = splat2(As[ty * 4 + r][kk]);
#pragma unroll
                for (int c = 0; c < 4; ++c) fma2(acc[r][c], asp, w2[c]);
            }
        }
        __syncthreads();
    }
#pragma unroll
    for (int r = 0; r < 4; ++r)
#pragma unroll
        for (int c = 0; c < 4; ++c) {
            float lo, hi; unpack2(acc[r][c], lo, hi);
            int row = ty * 4 + r;
            int col = j0 + tx * 8 + 2 * c;
            atomicAdd(&C[(size_t)row * UU + col], lo);
            atomicAdd(&C[(size_t)row * UU + col + 1], hi);
        }
}

__global__ void gemm_one(const float* __restrict__ A, int lda,
                         const float* __restrict__ W,
                         float* __restrict__ C, int K) {
    int kchunk = K / gridDim.y;
    gemm_core(A, lda, W, C, kchunk * blockIdx.y, kchunk * (blockIdx.y + 1));
}

__global__ void gemm_two(const float* __restrict__ A, int lda,
                         const float* __restrict__ W1, const float* __restrict__ W2,
                         float* __restrict__ C1, float* __restrict__ C2, int K) {
    int kchunk = K / gridDim.y;
    const float* W = blockIdx.z ? W2 : W1;
    float* C = blockIdx.z ? C2 : C1;
    gemm_core(A, lda, W, C, kchunk * blockIdx.y, kchunk * (blockIdx.y + 1));
}

// all 4 LSTM gates: combined = [cur | h_prev], K = 1024 split in chunks of 128
__global__ void gemm_gates(const float* __restrict__ cur,
                           const float* __restrict__ hprev,
                           const float* __restrict__ wf, const float* __restrict__ wi,
                           const float* __restrict__ wc, const float* __restrict__ wo,
                           float* __restrict__ g4) {
    int kb = blockIdx.y * 128, ke = kb + 128;
    const float* Wg = (blockIdx.z == 0) ? wf : (blockIdx.z == 1) ? wi
                    : (blockIdx.z == 2) ? wc : wo;
    const float* A = (kb < 512) ? cur : (hprev - 512);
    gemm_core(A, UU, Wg, g4 + (size_t)blockIdx.z * BB * UU, kb, ke);
}

// elementwise stages
__global__ void elu_kernel(const float* __restrict__ b1) {
    int i = blockIdx.x * blockDim.x + threadIdx.x;
    float v = d_c1[i] + b1[i & 511];
    d_h1[i] = v > 0.f ? v : expm1f(v);
}
__global__ void addbias_kernel(const float* __restrict__ b2) {
    int i = blockIdx.x * blockDim.x + threadIdx.x;
    d_h2[i] += b2[i & 511];
}

// fused GLU + layernorm (eps=1e-3) + softmax; stores attn/S. grid 64, block 512
__global__ void lnsm_kernel(const float* __restrict__ b3,
                            const float* __restrict__ b4,
                            const float* __restrict__ bskip,
                            const float* __restrict__ gamma,
                            const float* __restrict__ beta) {
    __shared__ float red[512];
    int b = blockIdx.x, t = threadIdx.x;
    int i = b * UU + t;
    float g = sigm(d_t3[i] + b3[t]);
    float v = d_c2[i] + bskip[t] + g * (d_t4[i] + b4[t]);
    red[t] = v; __syncthreads();
    for (int s = 256; s > 0; s >>= 1) { if (t < s) red[t] += red[t + s]; __syncthreads(); }
    float mu = red[0] * (1.f / 512.f);
    __syncthreads();
    float dv = v - mu;
    red[t] = dv * dv; __syncthreads();
    for (int s = 256; s > 0; s >>= 1) { if (t < s) red[t] += red[t + s]; __syncthreads(); }
    float var = red[0] * (1.f / 512.f);
    __syncthreads();
    float yn = dv * rsqrtf(var + 1e-3f) * gamma[t] + beta[t];
    red[t] = yn; __syncthreads();
    for (int s = 256; s > 0; s >>= 1) { if (t < s) red[t] = fmaxf(red[t], red[t + s]); __syncthreads(); }
    float m = red[0];
    __syncthreads();
    float e = __expf(yn - m);
    red[t] = e; __syncthreads();
    for (int s = 256; s > 0; s >>= 1) { if (t < s) red[t] += red[t + s]; __syncthreads(); }
    float inv = __fdividef(1.f, red[0] * 512.f);
    d_attn[b * UU + t] = e * inv;
}

// attention-weighted KAN feature aggregation. grid (64 b, 8 s-chunks), block 128
__global__ void agg_kernel(const float* __restrict__ in,
                           const float* __restrict__ tk) {
    __shared__ float ws[64], tks[64];
    int b = blockIdx.x;
    int s0 = blockIdx.y * 64;
    int f = threadIdx.x;
    if (f < 64) {
        ws[f]  = d_attn[b * UU + s0 + f];
        tks[f] = tk[s0 + f];
    }
    __syncthreads();
    float sacc = 0.f;
    float bacc[8] = {};
    const float* ip = in + (size_t)b * SS * FF + (size_t)s0 * FF + f;
    for (int si = 0; si < 64; ++si) {
        float x = tks[si] * ip[si * FF];
        float w = ws[si];
        float sg = sigm(x);
        sacc += w * (x * sg);
        float bs[8];
        bspline8(x, bs);
#pragma unroll
        for (int k = 0; k < 8; ++k) bacc[k] += w * bs[k];
    }
    atomicAdd(&d_aggs[b * FF + f], sacc);
#pragma unroll
    for (int k = 0; k < 8; ++k)
        atomicAdd(&d_aggb[(b * FF + f) * 8 + k], bacc[k]);
}

// spline_w (U, F*8) -> spT (F*8, U)
__global__ void transpose_kernel(const float* __restrict__ sw) {
    __shared__ float tile[32][33];
    int fk0 = blockIdx.x * 32, u0 = blockIdx.y * 32;
    int tx = threadIdx.x, ty = threadIdx.y;
    for (int r = ty; r < 32; r += 8)
        tile[r][tx] = sw[(size_t)(u0 + r) * 1024 + fk0 + tx];
    __syncthreads();
    for (int r = ty; r < 32; r += 8)
        d_spT[(size_t)(fk0 + r) * 512 + u0 + tx] = tile[tx][r];
}

// final LSTM cell; writes [h_new | c_new]
__global__ void lstm_kernel(const float* __restrict__ c_prev,
                            const float* __restrict__ bf,
                            const float* __restrict__ bi_,
                            const float* __restrict__ bc,
                            const float* __restrict__ bo,
                            float* __restrict__ out) {
    int i = blockIdx.x * blockDim.x + threadIdx.x;
    int u = i & 511;
    float f  = sigm(d_g4[i]              + bf [u]);
    float ig = sigm(d_g4[BB*UU + i]      + bi_[u]);
    float cd = tanhf(d_g4[2*BB*UU + i]   + bc [u]);
    float o  = sigm(d_g4[3*BB*UU + i]    + bo [u]);
    float cn = f * c_prev[i] + ig * cd;
    out[i] = o * tanhf(cn);
    out[BB*UU + i] = cn;
}

// ---------------- host ----------------
extern "C" void kernel_launch(void* const* d_in, const int* in_sizes, int n_in,
                              void* d_out, int out_size) {
    const float* in       = (const float*)d_in[0];
    const float* h_prev   = (const float*)d_in[1];
    const float* c_prev   = (const float*)d_in[2];
    const float* tk       = (const float*)d_in[3];
    const float* base_w   = (const float*)d_in[4];
    const float* spline_w = (const float*)d_in[5];
    const float* g_w1     = (const float*)d_in[6];
    const float* g_b1     = (const float*)d_in[7];
    const float* g_w2     = (const float*)d_in[8];
    const float* g_b2     = (const float*)d_in[9];
    const float* g_w3     = (const float*)d_in[10];
    const float* g_b3     = (const float*)d_in[11];
    const float* g_w4     = (const float*)d_in[12];
    const float* g_b4     = (const float*)d_in[13];
    const float* g_skip_w = (const float*)d_in[14];
    const float* g_skip_b = (const float*)d_in[15];
    const float* ln_gamma = (const float*)d_in[16];
    const float* ln_beta  = (const float*)d_in[17];
    const float* wf       = (const float*)d_in[18];
    const float* bf       = (const float*)d_in[19];
    const float* wi       = (const float*)d_in[20];
    const float* bi       = (const float*)d_in[21];
    const float* wc       = (const float*)d_in[22];
    const float* bc       = (const float*)d_in[23];
    const float* wo       = (const float*)d_in[24];
    const float* bo       = (const float*)d_in[25];
    float* out = (float*)d_out;
    (void)in_sizes; (void)n_in; (void)out_size;

    float *p_sig, *p_c1, *p_c2, *p_h1, *p_h2, *p_t3, *p_t4;
    float *p_aggs, *p_aggb, *p_cur, *p_spT, *p_g4;
    cudaGetSymbolAddress((void**)&p_sig,  d_sig);
    cudaGetSymbolAddress((void**)&p_c1,   d_c1);
    cudaGetSymbolAddress((void**)&p_c2,   d_c2);
    cudaGetSymbolAddress((void**)&p_h1,   d_h1);
    cudaGetSymbolAddress((void**)&p_h2,   d_h2);
    cudaGetSymbolAddress((void**)&p_t3,   d_t3);
    cudaGetSymbolAddress((void**)&p_t4,   d_t4);
    cudaGetSymbolAddress((void**)&p_aggs, d_aggs);
    cudaGetSymbolAddress((void**)&p_aggb, d_aggb);
    cudaGetSymbolAddress((void**)&p_cur,  d_cur);
    cudaGetSymbolAddress((void**)&p_spT,  d_spT);
    cudaGetSymbolAddress((void**)&p_g4,   d_g4);

    zero_kernel<<<256, 256>>>();
    transpose_kernel<<<dim3(32, 16), dim3(32, 8)>>>(spline_w);
    s2f_kernel<<<dim3(64, 2), 256>>>(in, tk);

    // sig @ g_w1 and sig @ g_skip_w in one launch (K = 16512, split 16)
    gemm_two<<<dim3(4, 16, 2), 256>>>(p_sig, SIGD, g_w1, g_skip_w, p_c1, p_c2, SIGD);

    elu_kernel<<<128, 256>>>(g_b1);
    gemm_one<<<dim3(4, 32), 256>>>(p_h1, UU, g_w2, p_h2, UU);
    addbias_kernel<<<128, 256>>>(g_b2);
    gemm_two<<<dim3(4, 16, 2), 256>>>(p_h2, UU, g_w3, g_w4, p_t3, p_t4, UU);
    lnsm_kernel<<<64, 512>>>(g_b3, g_b4, g_skip_b, ln_gamma, ln_beta);

    agg_kernel<<<dim3(64, 8), 128>>>(in, tk);

    // current = aggs @ base_w + aggb @ spline_wT
    gemm_one<<<dim3(4, 8),  256>>>(p_aggs, FF,     base_w, p_cur, FF);
    gemm_one<<<dim3(4, 32), 256>>>(p_aggb, FF * 8, p_spT,  p_cur, FF * 8);

    // gates: combined = [current | h_prev]
    gemm_gates<<<dim3(4, 8, 4), 256>>>(p_cur, h_prev, wf, wi, wc, wo, p_g4);

    lstm_kernel<<<128, 256>>>(c_prev, bf, bi, bc, bo, out);
}